// round 10
// baseline (speedup 1.0000x reference)
#include <cuda_runtime.h>
#include <math.h>

#define BB 128
#define TT 25
#define VOCAB 10000
#define EMBD 512
#define VGGD 4096
#define HIDD 512
#define GBLK 128

typedef unsigned long long u64;

// ---------------- packed f32x2 helpers (FFMA2: 2 MACs / instr) ---------------
__device__ __forceinline__ u64 pack2(float v) {
    u64 r; unsigned b = __float_as_uint(v);
    asm("mov.b64 %0, {%1, %1};" : "=l"(r) : "r"(b));
    return r;
}
__device__ __forceinline__ void fma2(u64& d, u64 a, u64 b) {
    asm("fma.rn.f32x2 %0, %1, %2, %0;" : "+l"(d) : "l"(a), "l"(b));
}
__device__ __forceinline__ float2 unpack2(u64 v) {
    unsigned lo, hi;
    asm("mov.b64 {%0, %1}, %2;" : "=r"(lo), "=r"(hi) : "l"(v));
    return make_float2(__uint_as_float(lo), __uint_as_float(hi));
}
__device__ __forceinline__ void unpack8(const u64 (&a2)[4], float (&a)[8]) {
#pragma unroll
    for (int j = 0; j < 4; j++) {
        float2 v = unpack2(a2[j]);
        a[2 * j] = v.x; a[2 * j + 1] = v.y;
    }
}

// ---------------- scratch (device globals; no allocation allowed) ------------
__device__ float g_h0[BB * HIDD];
__device__ float g_E[TT * BB * EMBD];          // gathered embeddings, row = t*B+b
__device__ float g_X0[TT * BB * 3 * HIDD];     // precomputed layer-0 input proj [u|r|c]
__device__ float g_S1[TT * BB * HIDD];         // s1 per step
__device__ float g_s0buf[2][BB * HIDD];        // s0 double buffer
__device__ float g_gu0[BB * HIDD];
__device__ float g_gr0[BB * HIDD];
__device__ float g_gu1[BB * HIDD];
__device__ float g_gr1[BB * HIDD];
__device__ float g_W0top[HIDD * 3 * HIDD];     // packed [Wu0_top|Wr0_top|Wc0_top]
__device__ float g_b0top[3 * HIDD];
__device__ unsigned g_bar_count;               // zero-init; returns to 0 each launch
__device__ unsigned g_bar_sense;               // toggles; read at kernel start

// ---------------- pack layer-0 top weights -----------------------------------
__global__ void pack_w0top(const float* __restrict__ Wu0, const float* __restrict__ Wr0,
                           const float* __restrict__ Wc0, const float* __restrict__ bu0,
                           const float* __restrict__ br0, const float* __restrict__ bc0) {
    int idx = blockIdx.x * blockDim.x + threadIdx.x;
    const int total = HIDD * 3 * HIDD;
    if (idx < total) {
        int k = idx / (3 * HIDD);
        int j = idx - k * (3 * HIDD);
        float v;
        if (j < HIDD)           v = Wu0[k * HIDD + j];
        else if (j < 2 * HIDD)  v = Wr0[k * HIDD + (j - HIDD)];
        else                    v = Wc0[k * HIDD + (j - 2 * HIDD)];
        g_W0top[idx] = v;
    }
    if (idx < 3 * HIDD) {
        g_b0top[idx] = (idx < HIDD) ? bu0[idx]
                     : (idx < 2 * HIDD) ? br0[idx - HIDD]
                                        : bc0[idx - 2 * HIDD];
    }
}

// ---------------- embedding gather -------------------------------------------
__global__ void embed_gather(const float* __restrict__ emb, const int* __restrict__ tokens) {
    int r = blockIdx.x;              // r = t*B + b
    int t = r / BB;
    int b = r - t * BB;
    int tok = tokens[b * TT + t];
    const float4* src = (const float4*)(emb + (size_t)tok * EMBD);
    float4* dst = (float4*)(g_E + (size_t)r * EMBD);
    dst[threadIdx.x] = src[threadIdx.x];   // 128 threads * float4 = 512 floats
}

// ---------------- big tiled SGEMM: C = A@W + bias (FFMA2 core) ---------------
template <int AREMAP>
__global__ __launch_bounds__(256) void sgemm_big(
    const float* __restrict__ A, const float* __restrict__ W,
    const float* __restrict__ bias, float* __restrict__ C,
    int M, int N, int K)
{
    __shared__ float As[8][128];
    __shared__ float Ws[8][128];
    int tid = threadIdx.x;
    int m0 = blockIdx.y * 128;
    int n0 = blockIdx.x * 128;
    int tx = tid & 15;
    int ty = tid >> 4;

    u64 acc2[8][4];
#pragma unroll
    for (int i = 0; i < 8; i++)
#pragma unroll
        for (int j = 0; j < 4; j++) acc2[i][j] = 0ull;

    int lar = tid >> 1;
    int lak = (tid & 1) * 4;
    int arow = m0 + lar;
    if (AREMAP) arow = (arow % TT) * BB + (arow / TT);
    const float* Aptr = A + (size_t)arow * K;
    int lwk = tid >> 5;
    int lwc = (tid & 31) * 4;

    for (int k0 = 0; k0 < K; k0 += 8) {
        float4 av = *(const float4*)(Aptr + k0 + lak);
        As[lak + 0][lar] = av.x;
        As[lak + 1][lar] = av.y;
        As[lak + 2][lar] = av.z;
        As[lak + 3][lar] = av.w;

        int wn = n0 + lwc;
        const float* Wp = W + (size_t)(k0 + lwk) * N + wn;
        float4 wv;
        if (wn + 3 < N) {
            wv = *(const float4*)Wp;
        } else {
            wv.x = (wn + 0 < N) ? Wp[0] : 0.f;
            wv.y = (wn + 1 < N) ? Wp[1] : 0.f;
            wv.z = (wn + 2 < N) ? Wp[2] : 0.f;
            wv.w = (wn + 3 < N) ? Wp[3] : 0.f;
        }
        *(float4*)&Ws[lwk][lwc] = wv;
        __syncthreads();

#pragma unroll
        for (int kk = 0; kk < 8; kk++) {
            float4 a0 = *(const float4*)&As[kk][ty * 4];
            float4 a1 = *(const float4*)&As[kk][64 + ty * 4];
            float4 w0 = *(const float4*)&Ws[kk][tx * 4];
            float4 w1 = *(const float4*)&Ws[kk][64 + tx * 4];
            u64 wv2[4];
            wv2[0] = ((const u64*)&w0)[0]; wv2[1] = ((const u64*)&w0)[1];
            wv2[2] = ((const u64*)&w1)[0]; wv2[3] = ((const u64*)&w1)[1];
            float ar[8] = {a0.x, a0.y, a0.z, a0.w, a1.x, a1.y, a1.z, a1.w};
#pragma unroll
            for (int i = 0; i < 8; i++) {
                u64 pa = pack2(ar[i]);
                fma2(acc2[i][0], pa, wv2[0]);
                fma2(acc2[i][1], pa, wv2[1]);
                fma2(acc2[i][2], pa, wv2[2]);
                fma2(acc2[i][3], pa, wv2[3]);
            }
        }
        __syncthreads();
    }

#pragma unroll
    for (int i = 0; i < 8; i++) {
        int row = m0 + ((i < 4) ? (ty * 4 + i) : (64 + ty * 4 + i - 4));
        float* Crow = C + (size_t)row * N;
#pragma unroll
        for (int j = 0; j < 4; j++) {
            float2 v = unpack2(acc2[i][j]);
            int col = n0 + ((j < 2) ? (tx * 4 + j * 2) : (64 + tx * 4 + (j - 2) * 2));
            if (col < N)     Crow[col]     = v.x + bias[col];
            if (col + 1 < N) Crow[col + 1] = v.y + bias[col + 1];
        }
    }
}

// ================== persistent recurrence kernel =============================
struct RP {
    const float* vgg;
    const float* W_in; const float* b_in;
    const float* Wu0; const float* Wr0; const float* Wc0;
    const float* Wu1; const float* Wr1; const float* Wc1;
    const float* bu1; const float* br1; const float* bc1;
};

// software grid barrier: all 128 blocks co-resident (grid <= 148 SMs)
__device__ __forceinline__ void gridbar(int tid, unsigned* ps) {
    __threadfence();
    __syncthreads();
    if (tid == 0) {
        unsigned ns = *ps ^ 1u;
        *ps = ns;
        if (atomicAdd(&g_bar_count, 1u) == GBLK - 1) {
            *(volatile unsigned*)&g_bar_count = 0;
            __threadfence();
            *(volatile unsigned*)&g_bar_sense = ns;
        } else {
            while (*(volatile unsigned*)&g_bar_sense != ns) { __nanosleep(32); }
        }
        __threadfence();
    }
    __syncthreads();
}

// A fetch: float4 from L2 (__ldcg), optional elementwise-mul second operand
__device__ __forceinline__ float4 ldA4(const float* pA, const float* pB, int k) {
    float4 a = __ldcg((const float4*)(pA + k));
    if (pB) {
        float4 b = __ldcg((const float4*)(pB + k));
        a.x *= b.x; a.y *= b.y; a.z *= b.z; a.w *= b.w;
    }
    return a;
}

// Per-thread row GEMM core (FFMA2): acc2[4] (8 cols) += A_row[0:KQ] @ W[0:KQ][8].
// A streamed from L2 (__ldcg, 16-k register pipeline); W direct __ldg — the
// 8-col weight slices stay L1-resident across all 25 time steps.
template <int KQ>
__device__ __forceinline__ void mm8t(u64 (&acc)[4],
    const float* pA, const float* pB, const float* __restrict__ gW)
{
    float4 buf[4];
#pragma unroll
    for (int i = 0; i < 4; i++) buf[i] = ldA4(pA, pB, i * 4);
#pragma unroll 1
    for (int g = 0; g < KQ; g += 16) {
#pragma unroll
        for (int s = 0; s < 4; s++) {
            float4 a = buf[s];
            int kb = g + s * 4 + 16;
            if (kb < KQ) buf[s] = ldA4(pA, pB, kb);
            const float* wp = gW + (size_t)(g + s * 4) * HIDD;
#pragma unroll
            for (int j = 0; j < 4; j++) {
                float4 w01 = __ldg((const float4*)(wp + (size_t)j * HIDD));
                float4 w23 = __ldg((const float4*)(wp + (size_t)j * HIDD + 4));
                u64 pa = pack2(j == 0 ? a.x : j == 1 ? a.y : j == 2 ? a.z : a.w);
                fma2(acc[0], pa, ((const u64*)&w01)[0]);
                fma2(acc[1], pa, ((const u64*)&w01)[1]);
                fma2(acc[2], pa, ((const u64*)&w23)[0]);
                fma2(acc[3], pa, ((const u64*)&w23)[1]);
            }
        }
    }
}

// cross-q partial reduction through smem
template <int MR, int Q>
__device__ __forceinline__ void reduceQ(float (&acc)[8], float* s, int m, int q) {
    __syncthreads();
    if (q > 0) {
        float* r = s + ((size_t)(q - 1) * MR + m) * 8;
        *(float4*)r       = make_float4(acc[0], acc[1], acc[2], acc[3]);
        *(float4*)(r + 4) = make_float4(acc[4], acc[5], acc[6], acc[7]);
    }
    __syncthreads();
    if (q == 0) {
#pragma unroll
        for (int qq = 1; qq < Q; qq++) {
            const float* r = s + ((size_t)(qq - 1) * MR + m) * 8;
#pragma unroll
            for (int j = 0; j < 8; j++) acc[j] += r[j];
        }
    }
}

__device__ __forceinline__ float sigm(float x) { return 1.f / (1.f + expf(-x)); }

__global__ __launch_bounds__(512, 1) void recur_kernel(RP p) {
    __shared__ float sred[3584];      // 14 KB reduction scratch
    __shared__ unsigned s_sense;
    int tid = threadIdx.x, bid = blockIdx.x;
    if (tid == 0) s_sense = *(volatile unsigned*)&g_bar_sense;
    __syncthreads();

    // ---- phase h0: tanh(vgg @ W_in + b_in)  MR=64, Q=8, K=4096 ----
    {
        int ct = bid >> 1, rg = bid & 1;
        int c0 = ct * 8;
        int m = tid & 63, q = tid >> 6;          // q 0..7
        int row = rg * 64 + m;
        const float* pA = p.vgg + (size_t)row * VGGD + q * 512;
        const float* gW = p.W_in + (size_t)(q * 512) * HIDD + c0;
        u64 a2[4] = {0, 0, 0, 0};
        mm8t<512>(a2, pA, nullptr, gW);
        float acc[8]; unpack8(a2, acc);
        reduceQ<64, 8>(acc, sred, m, q);
        if (q == 0) {
#pragma unroll
            for (int j = 0; j < 8; j++)
                g_h0[row * HIDD + c0 + j] = tanhf(acc[j] + __ldg(p.b_in + c0 + j));
        }
    }
    gridbar(tid, &s_sense);

#pragma unroll 1
    for (int t = 0; t < TT; t++) {
        const float* s0prev = (t == 0) ? g_h0 : g_s0buf[(t - 1) & 1];
        float*       s0cur  = g_s0buf[t & 1];
        const float* s1prev = (t == 0) ? g_h0 : (g_S1 + (size_t)(t - 1) * BB * HIDD);
        float*       s1cur  = g_S1 + (size_t)t * BB * HIDD;
        const float* X0t    = g_X0 + (size_t)t * BB * 3 * HIDD;

        // ---- P1: gu0|gr0 = sigmoid(X0[u|r] + s0prev @ W{u,r}0_bot)  MR=128,Q=4,K=512
        {
            int c0g = bid * 8;
            int half = c0g >= HIDD;
            int wcol = c0g & (HIDD - 1);
            const float* Wg = (half ? p.Wr0 : p.Wu0) + HIDD * HIDD;
            int m = tid & 127, q = tid >> 7;     // q 0..3
            const float* pA = s0prev + (size_t)m * HIDD + q * 128;
            const float* gW = Wg + (size_t)(q * 128) * HIDD + wcol;
            u64 a2[4] = {0, 0, 0, 0};
            mm8t<128>(a2, pA, nullptr, gW);
            float acc[8]; unpack8(a2, acc);
            reduceQ<128, 4>(acc, sred, m, q);
            if (q == 0) {
                float* out = half ? g_gr0 : g_gu0;
                const float* xp = X0t + (size_t)m * 3 * HIDD + c0g;
                float* op = out + (size_t)m * HIDD + wcol;
#pragma unroll
                for (int j = 0; j < 8; j++) op[j] = sigm(acc[j] + __ldcg(xp + j));
            }
        }
        gridbar(tid, &s_sense);

        // ---- P2: s0cur = gu0*s0 + (1-gu0)*tanh(X0[c] + (gr0*s0)@Wc0_bot)  MR=64,Q=8,K=512
        {
            int ct = bid >> 1, rg = bid & 1;
            int c0 = ct * 8;
            int m = tid & 63, q = tid >> 6;      // q 0..7
            int row = rg * 64 + m;
            const float* pA = g_gr0 + (size_t)row * HIDD + q * 64;
            const float* pB = s0prev + (size_t)row * HIDD + q * 64;
            const float* gW = p.Wc0 + HIDD * HIDD + (size_t)(q * 64) * HIDD + c0;
            u64 a2[4] = {0, 0, 0, 0};
            mm8t<64>(a2, pA, pB, gW);
            float acc[8]; unpack8(a2, acc);
            reduceQ<64, 8>(acc, sred, m, q);
            if (q == 0) {
                const float* xp = X0t + (size_t)row * 3 * HIDD + 2 * HIDD + c0;
#pragma unroll
                for (int j = 0; j < 8; j++) {
                    float c  = tanhf(acc[j] + __ldcg(xp + j));
                    float gu = __ldcg(g_gu0 + (size_t)row * HIDD + c0 + j);
                    float h  = __ldcg(s0prev + (size_t)row * HIDD + c0 + j);
                    s0cur[(size_t)row * HIDD + c0 + j] = gu * h + (1.f - gu) * c;
                }
            }
        }
        gridbar(tid, &s_sense);

        // ---- P3: gu1|gr1 = sigmoid([s0cur|s1prev] @ W{u,r}1 + b)  MR=128,Q=4,K=1024
        {
            int c0g = bid * 8;
            int half = c0g >= HIDD;
            int wcol = c0g & (HIDD - 1);
            const float* Wg = half ? p.Wr1 : p.Wu1;
            int m = tid & 127, q = tid >> 7;     // q 0..3; q<2 → s0cur, q>=2 → s1prev
            const float* pA = (q < 2) ? (s0cur + (size_t)m * HIDD + q * 256)
                                      : (s1prev + (size_t)m * HIDD + (q - 2) * 256);
            const float* gW = Wg + (size_t)(q * 256) * HIDD + wcol;
            u64 a2[4] = {0, 0, 0, 0};
            mm8t<256>(a2, pA, nullptr, gW);
            float acc[8]; unpack8(a2, acc);
            reduceQ<128, 4>(acc, sred, m, q);
            if (q == 0) {
                const float* b = half ? p.br1 : p.bu1;
                float* out = half ? g_gr1 : g_gu1;
                float* op = out + (size_t)m * HIDD + wcol;
#pragma unroll
                for (int j = 0; j < 8; j++) op[j] = sigm(acc[j] + __ldg(b + wcol + j));
            }
        }
        gridbar(tid, &s_sense);

        // ---- P4: s1cur = gu1*s1 + (1-gu1)*tanh([s0cur|gr1*s1]@Wc1 + bc1)  MR=64,Q=8,K=1024
        {
            int ct = bid >> 1, rg = bid & 1;
            int c0 = ct * 8;
            int m = tid & 63, q = tid >> 6;      // q 0..7; q<4 → s0cur, q>=4 → gr1*s1prev
            int row = rg * 64 + m;
            const float* pA;
            const float* pB = nullptr;
            if (q < 4) {
                pA = s0cur + (size_t)row * HIDD + q * 128;
            } else {
                pA = g_gr1 + (size_t)row * HIDD + (q - 4) * 128;
                pB = s1prev + (size_t)row * HIDD + (q - 4) * 128;
            }
            const float* gW = p.Wc1 + (size_t)(q * 128) * HIDD + c0;
            u64 a2[4] = {0, 0, 0, 0};
            mm8t<128>(a2, pA, pB, gW);
            float acc[8]; unpack8(a2, acc);
            reduceQ<64, 8>(acc, sred, m, q);
            if (q == 0) {
#pragma unroll
                for (int j = 0; j < 8; j++) {
                    float c  = tanhf(acc[j] + __ldg(p.bc1 + c0 + j));
                    float gu = __ldcg(g_gu1 + (size_t)row * HIDD + c0 + j);
                    float h  = __ldcg(s1prev + (size_t)row * HIDD + c0 + j);
                    s1cur[(size_t)row * HIDD + c0 + j] = gu * h + (1.f - gu) * c;
                }
            }
        }
        gridbar(tid, &s_sense);
    }
}

// ---------------- final state write ------------------------------------------
__global__ void write_state(float* __restrict__ out) {
    int idx = blockIdx.x * blockDim.x + threadIdx.x;
    if (idx < BB * HIDD) {
        size_t base = (size_t)BB * TT * VOCAB;
        out[base + idx] = g_s0buf[(TT - 1) & 1][idx];
        out[base + BB * HIDD + idx] = g_S1[(size_t)(TT - 1) * BB * HIDD + idx];
    }
}

// ---------------- host driver -------------------------------------------------
template <typename Sym>
static float* sym(Sym& s) {
    void* p = nullptr;
    cudaGetSymbolAddress(&p, s);
    return (float*)p;
}

extern "C" void kernel_launch(void* const* d_in, const int* in_sizes, int n_in,
                              void* d_out, int out_size) {
    const float* vgg     = (const float*)d_in[0];
    const int*   xTokens = (const int*)d_in[1];
    int i = 2;
    if (n_in >= 20 && in_sizes[2] == 1) i = 3;   // skip is_train scalar
    const float* emb   = (const float*)d_in[i++];
    const float* W_in  = (const float*)d_in[i++];
    const float* b_in  = (const float*)d_in[i++];
    const float* Wu0   = (const float*)d_in[i++];
    const float* bu0   = (const float*)d_in[i++];
    const float* Wr0   = (const float*)d_in[i++];
    const float* br0   = (const float*)d_in[i++];
    const float* Wc0   = (const float*)d_in[i++];
    const float* bc0   = (const float*)d_in[i++];
    const float* Wu1   = (const float*)d_in[i++];
    const float* bu1   = (const float*)d_in[i++];
    const float* Wr1   = (const float*)d_in[i++];
    const float* br1   = (const float*)d_in[i++];
    const float* Wc1   = (const float*)d_in[i++];
    const float* bc1   = (const float*)d_in[i++];
    const float* W_out = (const float*)d_in[i++];
    const float* b_out = (const float*)d_in[i++];
    float* out = (float*)d_out;

    float* pE     = sym(g_E);
    float* pX0    = sym(g_X0);
    float* pS1    = sym(g_S1);
    float* pW0top = sym(g_W0top);
    float* pB0top = sym(g_b0top);

    // 1) pack layer-0 top weights + biases
    pack_w0top<<<(HIDD * 3 * HIDD + 255) / 256, 256>>>(Wu0, Wr0, Wc0, bu0, br0, bc0);

    // 2) embedding gather
    embed_gather<<<TT * BB, 128>>>(emb, xTokens);

    // 3) X0 = E_all @ W0top + b0top   [3200,512]@[512,1536]
    sgemm_big<0><<<dim3(3 * HIDD / 128, TT * BB / 128), 256>>>(
        pE, pW0top, pB0top, pX0, TT * BB, 3 * HIDD, HIDD);

    // 4) persistent recurrence (h0 + 25 GRU steps, software grid barriers)
    {
        RP rp;
        rp.vgg = vgg; rp.W_in = W_in; rp.b_in = b_in;
        rp.Wu0 = Wu0; rp.Wr0 = Wr0; rp.Wc0 = Wc0;
        rp.Wu1 = Wu1; rp.Wr1 = Wr1; rp.Wc1 = Wc1;
        rp.bu1 = bu1; rp.br1 = br1; rp.bc1 = bc1;
        recur_kernel<<<GBLK, 512>>>(rp);
    }

    // 5) logits = S1 @ W_out + b_out, output rows in (b*T+t) order via A-remap
    sgemm_big<1><<<dim3((VOCAB + 127) / 128, TT * BB / 128), 256>>>(
        pS1, W_out, b_out, out, TT * BB, VOCAB, HIDD);

    // 6) final state [2, B, HID]
    write_state<<<(BB * HIDD + 255) / 256, 256>>>(out);
}

// round 12
// speedup vs baseline: 1.4493x; 1.4493x over previous
#include <cuda_runtime.h>
#include <math.h>

#define BB 128
#define TT 25
#define VOCAB 10000
#define EMBD 512
#define VGGD 4096
#define HIDD 512
#define GBLK 128

typedef unsigned long long u64;

// ---------------- packed f32x2 helpers (FFMA2: 2 MACs / instr) ---------------
__device__ __forceinline__ u64 pack2(float v) {
    u64 r; unsigned b = __float_as_uint(v);
    asm("mov.b64 %0, {%1, %1};" : "=l"(r) : "r"(b));
    return r;
}
__device__ __forceinline__ void fma2(u64& d, u64 a, u64 b) {
    asm("fma.rn.f32x2 %0, %1, %2, %0;" : "+l"(d) : "l"(a), "l"(b));
}
__device__ __forceinline__ float2 unpack2(u64 v) {
    unsigned lo, hi;
    asm("mov.b64 {%0, %1}, %2;" : "=r"(lo), "=r"(hi) : "l"(v));
    return make_float2(__uint_as_float(lo), __uint_as_float(hi));
}
__device__ __forceinline__ void unpack8(const u64 (&a2)[4], float (&a)[8]) {
#pragma unroll
    for (int j = 0; j < 4; j++) {
        float2 v = unpack2(a2[j]);
        a[2 * j] = v.x; a[2 * j + 1] = v.y;
    }
}
__device__ __forceinline__ void unpack4(const u64 (&a2)[2], float (&a)[4]) {
#pragma unroll
    for (int j = 0; j < 2; j++) {
        float2 v = unpack2(a2[j]);
        a[2 * j] = v.x; a[2 * j + 1] = v.y;
    }
}

// ---------------- scratch (device globals; no allocation allowed) ------------
__device__ float g_h0[BB * HIDD];
__device__ float g_E[TT * BB * EMBD];
__device__ float g_X0[TT * BB * 3 * HIDD];     // [u|r|c] per row
__device__ float g_S1[TT * BB * HIDD];
__device__ float g_s0buf[2][BB * HIDD];
__device__ float g_gu0[BB * HIDD];
__device__ float g_gr0[BB * HIDD];
__device__ float g_gu1[BB * HIDD];
__device__ float g_gr1[BB * HIDD];
__device__ float g_W0top[HIDD * 3 * HIDD];
__device__ float g_b0top[3 * HIDD];
__device__ unsigned g_bar_count;
__device__ unsigned g_bar_sense;

// ---------------- pack layer-0 top weights -----------------------------------
__global__ void pack_w0top(const float* __restrict__ Wu0, const float* __restrict__ Wr0,
                           const float* __restrict__ Wc0, const float* __restrict__ bu0,
                           const float* __restrict__ br0, const float* __restrict__ bc0) {
    int idx = blockIdx.x * blockDim.x + threadIdx.x;
    const int total = HIDD * 3 * HIDD;
    if (idx < total) {
        int k = idx / (3 * HIDD);
        int j = idx - k * (3 * HIDD);
        float v;
        if (j < HIDD)           v = Wu0[k * HIDD + j];
        else if (j < 2 * HIDD)  v = Wr0[k * HIDD + (j - HIDD)];
        else                    v = Wc0[k * HIDD + (j - 2 * HIDD)];
        g_W0top[idx] = v;
    }
    if (idx < 3 * HIDD) {
        g_b0top[idx] = (idx < HIDD) ? bu0[idx]
                     : (idx < 2 * HIDD) ? br0[idx - HIDD]
                                        : bc0[idx - 2 * HIDD];
    }
}

// ---------------- embedding gather -------------------------------------------
__global__ void embed_gather(const float* __restrict__ emb, const int* __restrict__ tokens) {
    int r = blockIdx.x;
    int t = r / BB;
    int b = r - t * BB;
    int tok = tokens[b * TT + t];
    const float4* src = (const float4*)(emb + (size_t)tok * EMBD);
    float4* dst = (float4*)(g_E + (size_t)r * EMBD);
    dst[threadIdx.x] = src[threadIdx.x];
}

// ---------------- big tiled SGEMM: C = A@W + bias (FFMA2 core) ---------------
template <int AREMAP>
__global__ __launch_bounds__(256) void sgemm_big(
    const float* __restrict__ A, const float* __restrict__ W,
    const float* __restrict__ bias, float* __restrict__ C,
    int M, int N, int K)
{
    __shared__ float As[8][128];
    __shared__ float Ws[8][128];
    int tid = threadIdx.x;
    int m0 = blockIdx.y * 128;
    int n0 = blockIdx.x * 128;
    int tx = tid & 15;
    int ty = tid >> 4;

    u64 acc2[8][4];
#pragma unroll
    for (int i = 0; i < 8; i++)
#pragma unroll
        for (int j = 0; j < 4; j++) acc2[i][j] = 0ull;

    int lar = tid >> 1;
    int lak = (tid & 1) * 4;
    int arow = m0 + lar;
    if (AREMAP) arow = (arow % TT) * BB + (arow / TT);
    const float* Aptr = A + (size_t)arow * K;
    int lwk = tid >> 5;
    int lwc = (tid & 31) * 4;

    for (int k0 = 0; k0 < K; k0 += 8) {
        float4 av = *(const float4*)(Aptr + k0 + lak);
        As[lak + 0][lar] = av.x;
        As[lak + 1][lar] = av.y;
        As[lak + 2][lar] = av.z;
        As[lak + 3][lar] = av.w;

        int wn = n0 + lwc;
        const float* Wp = W + (size_t)(k0 + lwk) * N + wn;
        float4 wv;
        if (wn + 3 < N) {
            wv = *(const float4*)Wp;
        } else {
            wv.x = (wn + 0 < N) ? Wp[0] : 0.f;
            wv.y = (wn + 1 < N) ? Wp[1] : 0.f;
            wv.z = (wn + 2 < N) ? Wp[2] : 0.f;
            wv.w = (wn + 3 < N) ? Wp[3] : 0.f;
        }
        *(float4*)&Ws[lwk][lwc] = wv;
        __syncthreads();

#pragma unroll
        for (int kk = 0; kk < 8; kk++) {
            float4 a0 = *(const float4*)&As[kk][ty * 4];
            float4 a1 = *(const float4*)&As[kk][64 + ty * 4];
            float4 w0 = *(const float4*)&Ws[kk][tx * 4];
            float4 w1 = *(const float4*)&Ws[kk][64 + tx * 4];
            u64 wv2[4];
            wv2[0] = ((const u64*)&w0)[0]; wv2[1] = ((const u64*)&w0)[1];
            wv2[2] = ((const u64*)&w1)[0]; wv2[3] = ((const u64*)&w1)[1];
            float ar[8] = {a0.x, a0.y, a0.z, a0.w, a1.x, a1.y, a1.z, a1.w};
#pragma unroll
            for (int i = 0; i < 8; i++) {
                u64 pa = pack2(ar[i]);
                fma2(acc2[i][0], pa, wv2[0]);
                fma2(acc2[i][1], pa, wv2[1]);
                fma2(acc2[i][2], pa, wv2[2]);
                fma2(acc2[i][3], pa, wv2[3]);
            }
        }
        __syncthreads();
    }

#pragma unroll
    for (int i = 0; i < 8; i++) {
        int row = m0 + ((i < 4) ? (ty * 4 + i) : (64 + ty * 4 + i - 4));
        float* Crow = C + (size_t)row * N;
#pragma unroll
        for (int j = 0; j < 4; j++) {
            float2 v = unpack2(acc2[i][j]);
            int col = n0 + ((j < 2) ? (tx * 4 + j * 2) : (64 + tx * 4 + (j - 2) * 2));
            if (col < N)     Crow[col]     = v.x + bias[col];
            if (col + 1 < N) Crow[col + 1] = v.y + bias[col + 1];
        }
    }
}

// ================== persistent recurrence kernel =============================
struct RP {
    const float* vgg;
    const float* W_in; const float* b_in;
    const float* Wu0; const float* Wr0; const float* Wc0;
    const float* Wu1; const float* Wr1; const float* Wc1;
    const float* bu1; const float* br1; const float* bc1;
};

__device__ __forceinline__ void gridbar(int tid, unsigned* ps) {
    __threadfence();
    __syncthreads();
    if (tid == 0) {
        unsigned ns = *ps ^ 1u;
        *ps = ns;
        if (atomicAdd(&g_bar_count, 1u) == GBLK - 1) {
            *(volatile unsigned*)&g_bar_count = 0;
            __threadfence();
            *(volatile unsigned*)&g_bar_sense = ns;
        } else {
            while (*(volatile unsigned*)&g_bar_sense != ns) { }
        }
        __threadfence();
    }
    __syncthreads();
}

// ---- stage one 64-k A chunk [128 rows] into smem (coalesced, optional ⊙) ----
__device__ __forceinline__ void stageA64(float* dst, const float* __restrict__ s1,
                                         const float* __restrict__ s2,
                                         int kbase, int tid) {
#pragma unroll
    for (int i = 0; i < 4; i++) {
        int lin = tid + i * 512;
        int row = lin >> 4, f4 = (lin & 15) * 4;
        float4 v = __ldcg((const float4*)(s1 + (size_t)row * HIDD + kbase + f4));
        if (s2) {
            float4 b = __ldcg((const float4*)(s2 + (size_t)row * HIDD + kbase + f4));
            v.x *= b.x; v.y *= b.y; v.z *= b.z; v.w *= b.w;
        }
        *(float4*)(dst + row * 68 + f4) = v;
    }
}

// ---- per-thread 16-k accumulate: C output cols, W broadcast from smem -------
template <int C>
__device__ __forceinline__ void accumC(u64* acc, const float* Arow, const float* Wk) {
#pragma unroll
    for (int kk = 0; kk < 16; kk += 4) {
        float4 a = *(const float4*)(Arow + kk);
        float av[4] = {a.x, a.y, a.z, a.w};
#pragma unroll
        for (int j = 0; j < 4; j++) {
            const u64* w = (const u64*)(Wk + (kk + j) * C);
            u64 pa = pack2(av[j]);
#pragma unroll
            for (int c = 0; c < C / 2; c++) fma2(acc[c], pa, w[c]);
        }
    }
}

// ---- cross-q (4-way) reduction via smem -------------------------------------
template <int C>
__device__ __forceinline__ void reduceC(float* acc, float* sred, int m, int q) {
    __syncthreads();
    if (q > 0) {
        float* r = sred + ((size_t)(q - 1) * 128 + m) * C;
#pragma unroll
        for (int j = 0; j < C; j++) r[j] = acc[j];
    }
    __syncthreads();
    if (q == 0) {
#pragma unroll
        for (int qq = 1; qq < 4; qq++) {
            const float* r = sred + ((size_t)(qq - 1) * 128 + m) * C;
#pragma unroll
            for (int j = 0; j < C; j++) acc[j] += r[j];
        }
    }
}

// helpers for h0 (one-time, K=4096)
__device__ __forceinline__ float4 ldA4(const float* pA, int k) {
    return __ldcg((const float4*)(pA + k));
}
template <int KQ>
__device__ __forceinline__ void mm8t(u64 (&acc)[4], const float* pA,
                                     const float* __restrict__ gW) {
#pragma unroll 1
    for (int g = 0; g < KQ; g += 4) {
        float4 a = ldA4(pA, g);
        const float* wp = gW + (size_t)g * HIDD;
#pragma unroll
        for (int j = 0; j < 4; j++) {
            float4 w01 = __ldg((const float4*)(wp + (size_t)j * HIDD));
            float4 w23 = __ldg((const float4*)(wp + (size_t)j * HIDD + 4));
            u64 pa = pack2(j == 0 ? a.x : j == 1 ? a.y : j == 2 ? a.z : a.w);
            fma2(acc[0], pa, ((const u64*)&w01)[0]);
            fma2(acc[1], pa, ((const u64*)&w01)[1]);
            fma2(acc[2], pa, ((const u64*)&w23)[0]);
            fma2(acc[3], pa, ((const u64*)&w23)[1]);
        }
    }
}
template <int MR, int Q>
__device__ __forceinline__ void reduceQ(float (&acc)[8], float* s, int m, int q) {
    __syncthreads();
    if (q > 0) {
        float* r = s + ((size_t)(q - 1) * MR + m) * 8;
        *(float4*)r       = make_float4(acc[0], acc[1], acc[2], acc[3]);
        *(float4*)(r + 4) = make_float4(acc[4], acc[5], acc[6], acc[7]);
    }
    __syncthreads();
    if (q == 0) {
#pragma unroll
        for (int qq = 1; qq < Q; qq++) {
            const float* r = s + ((size_t)(qq - 1) * MR + m) * 8;
#pragma unroll
            for (int j = 0; j < 8; j++) acc[j] += r[j];
        }
    }
}

__device__ __forceinline__ float sigm(float x) { return 1.f / (1.f + expf(-x)); }

// smem layout (floats):
//  sWg1  [1024*8]  gates1 weight slice ([Wu1|Wr1] cols c0g..c0g+8)
//  sWc1t [512*4]   Wc1 top-half cols cc..cc+4
//  sWc1b [512*4]   Wc1 bottom-half
//  sWg0  [512*8]   gates0 bottom-half slice
//  sWc0b [512*4]   Wc0 bottom-half
//  sA0   [128*68]  A chunk buffer
//  sA1   [128*68]  A chunk buffer 2
//  sred  [3584]    reduction scratch
#define SM_WG1   0
#define SM_WC1T  8192
#define SM_WC1B  10240
#define SM_WG0   12288
#define SM_WC0B  16384
#define SM_A0    18432
#define SM_A1    27136
#define SM_RED   35840
#define SM_TOTALF 39424

__global__ __launch_bounds__(512, 1) void recur_kernel(RP p) {
    extern __shared__ float sm[];
    float* sWg1  = sm + SM_WG1;
    float* sWc1t = sm + SM_WC1T;
    float* sWc1b = sm + SM_WC1B;
    float* sWg0  = sm + SM_WG0;
    float* sWc0b = sm + SM_WC0B;
    float* sA0   = sm + SM_A0;
    float* sA1   = sm + SM_A1;
    float* sred  = sm + SM_RED;
    __shared__ unsigned s_sense;

    int tid = threadIdx.x, bid = blockIdx.x;
    if (tid == 0) s_sense = *(volatile unsigned*)&g_bar_sense;

    const int c0g  = bid * 8;                 // gates col base in [0,1024)
    const int half = c0g >= HIDD;
    const int wcol = c0g & (HIDD - 1);
    const int cc   = bid * 4;                 // candidate col base in [0,512)
    const int m = tid & 127, q = tid >> 7;    // row, K-quarter

    // ---- stage all weight slices once -----------------------------------
    {
        const float* Wg1 = half ? p.Wr1 : p.Wu1;
        for (int lin = tid; lin < 2048; lin += 512) {
            int k = lin >> 1, j4 = (lin & 1) * 4;
            *(float4*)(sWg1 + k * 8 + j4) =
                __ldg((const float4*)(Wg1 + (size_t)k * HIDD + wcol + j4));
        }
        const float* Wg0 = (half ? p.Wr0 : p.Wu0) + HIDD * HIDD;
        for (int lin = tid; lin < 1024; lin += 512) {
            int k = lin >> 1, j4 = (lin & 1) * 4;
            *(float4*)(sWg0 + k * 8 + j4) =
                __ldg((const float4*)(Wg0 + (size_t)k * HIDD + wcol + j4));
        }
        {
            int k = tid;
            if (k < 512) {
                *(float4*)(sWc1t + k * 4) =
                    __ldg((const float4*)(p.Wc1 + (size_t)k * HIDD + cc));
                *(float4*)(sWc1b + k * 4) =
                    __ldg((const float4*)(p.Wc1 + (size_t)(512 + k) * HIDD + cc));
                *(float4*)(sWc0b + k * 4) =
                    __ldg((const float4*)(p.Wc0 + (size_t)(512 + k) * HIDD + cc));
            }
        }
    }
    __syncthreads();

    // ---- h0 = tanh(vgg @ W_in + b_in)  MR=64, Q=8, K=4096 ----------------
    {
        int ct = bid >> 1, rg = bid & 1;
        int c0 = ct * 8;
        int hm = tid & 63, hq = tid >> 6;     // hq 0..7
        int row = rg * 64 + hm;
        const float* pA = p.vgg + (size_t)row * VGGD + hq * 512;
        const float* gW = p.W_in + (size_t)(hq * 512) * HIDD + c0;
        u64 a2[4] = {0, 0, 0, 0};
        mm8t<512>(a2, pA, gW);
        float acc[8]; unpack8(a2, acc);
        reduceQ<64, 8>(acc, sred, hm, hq);
        if (hq == 0) {
#pragma unroll
            for (int j = 0; j < 8; j++)
                g_h0[row * HIDD + c0 + j] = tanhf(acc[j] + __ldg(p.b_in + c0 + j));
        }
    }
    gridbar(tid, &s_sense);

    // ---- prologue 1: gates0(0) from h0 -----------------------------------
    {
        u64 aG0[4] = {0, 0, 0, 0};
        for (int ch = 0; ch < 8; ch++) {
            int kb = ch * 64;
            stageA64(sA0, g_h0, nullptr, kb, tid);
            __syncthreads();
            accumC<8>(aG0, sA0 + m * 68 + q * 16, sWg0 + (kb + q * 16) * 8);
            __syncthreads();
        }
        float g0[8]; unpack8(aG0, g0);
        reduceC<8>(g0, sred, m, q);
        if (q == 0) {
            float* out = half ? g_gr0 : g_gu0;
            const float* xp = g_X0 + (size_t)m * 3 * HIDD + c0g;
#pragma unroll
            for (int j = 0; j < 8; j++)
                out[m * HIDD + wcol + j] = sigm(g0[j] + __ldg(xp + j));
        }
    }
    gridbar(tid, &s_sense);

    // ---- prologue 2: s0cur(0) --------------------------------------------
    {
        u64 aC0[2] = {0, 0};
        for (int ch = 0; ch < 8; ch++) {
            int kb = ch * 64;
            stageA64(sA0, g_gr0, g_h0, kb, tid);
            __syncthreads();
            accumC<4>(aC0, sA0 + m * 68 + q * 16, sWc0b + (kb + q * 16) * 4);
            __syncthreads();
        }
        float c0v[4]; unpack4(aC0, c0v);
        reduceC<4>(c0v, sred, m, q);
        if (q == 0) {
#pragma unroll
            for (int j = 0; j < 4; j++) {
                int col = cc + j;
                float c  = tanhf(c0v[j] + __ldg(g_X0 + (size_t)m * 3 * HIDD + 2 * HIDD + col));
                float gu = __ldcg(g_gu0 + (size_t)m * HIDD + col);
                float h  = __ldcg(g_h0 + (size_t)m * HIDD + col);
                g_s0buf[0][(size_t)m * HIDD + col] = gu * h + (1.f - gu) * c;
            }
        }
    }
    gridbar(tid, &s_sense);

    // ---- main loop: 2 phases / step --------------------------------------
#pragma unroll 1
    for (int t = 0; t < TT; t++) {
        const float* s0c = g_s0buf[t & 1];
        const float* s1p = t ? (g_S1 + (size_t)(t - 1) * BB * HIDD) : g_h0;
        const float* X0n = g_X0 + (size_t)(t + 1) * BB * 3 * HIDD;
        const bool last = (t == TT - 1);

        u64 aC1[2] = {0, 0};

        // ===== PhA: gates1(t) + c1-top(t) + gates0(t+1) =====
        {
            u64 aG1[4] = {0, 0, 0, 0};
            for (int ch = 0; ch < 16; ch++) {
                int kb = ch * 64;
                const float* src = (kb < HIDD) ? s0c : s1p;
                stageA64(sA0, src, nullptr, kb & (HIDD - 1), tid);
                __syncthreads();
                accumC<8>(aG1, sA0 + m * 68 + q * 16, sWg1 + (kb + q * 16) * 8);
                __syncthreads();
            }
            float g1[8]; unpack8(aG1, g1);
            reduceC<8>(g1, sred, m, q);
            if (q == 0) {
                const float* b = half ? p.br1 : p.bu1;
                float* out = half ? g_gr1 : g_gu1;
#pragma unroll
                for (int j = 0; j < 8; j++)
                    out[m * HIDD + wcol + j] = sigm(g1[j] + __ldg(b + wcol + j));
            }

            u64 aG0[4] = {0, 0, 0, 0};
            for (int ch = 0; ch < 8; ch++) {
                int kb = ch * 64;
                stageA64(sA0, s0c, nullptr, kb, tid);
                __syncthreads();
                accumC<4>(aC1, sA0 + m * 68 + q * 16, sWc1t + (kb + q * 16) * 4);
                if (!last)
                    accumC<8>(aG0, sA0 + m * 68 + q * 16, sWg0 + (kb + q * 16) * 8);
                __syncthreads();
            }
            if (!last) {
                float g0[8]; unpack8(aG0, g0);
                reduceC<8>(g0, sred, m, q);
                if (q == 0) {
                    float* out = half ? g_gr0 : g_gu0;
#pragma unroll
                    for (int j = 0; j < 8; j++)
                        out[m * HIDD + wcol + j] =
                            sigm(g0[j] + __ldg(X0n + (size_t)m * 3 * HIDD + c0g + j));
                }
            }
        }
        gridbar(tid, &s_sense);

        // ===== PhB: s1cur(t) + s0cur(t+1) =====
        {
            u64 aC0[2] = {0, 0};
            for (int ch = 0; ch < 8; ch++) {
                int kb = ch * 64;
                stageA64(sA0, g_gr1, s1p, kb, tid);
                if (!last) stageA64(sA1, g_gr0, s0c, kb, tid);
                __syncthreads();
                accumC<4>(aC1, sA0 + m * 68 + q * 16, sWc1b + (kb + q * 16) * 4);
                if (!last)
                    accumC<4>(aC0, sA1 + m * 68 + q * 16, sWc0b + (kb + q * 16) * 4);
                __syncthreads();
            }
            float c1v[4]; unpack4(aC1, c1v);
            reduceC<4>(c1v, sred, m, q);
            if (q == 0) {
                float* s1cur = g_S1 + (size_t)t * BB * HIDD;
#pragma unroll
                for (int j = 0; j < 4; j++) {
                    int col = cc + j;
                    float c  = tanhf(c1v[j] + __ldg(p.bc1 + col));
                    float gu = __ldcg(g_gu1 + (size_t)m * HIDD + col);
                    float h  = __ldcg(s1p + (size_t)m * HIDD + col);
                    s1cur[(size_t)m * HIDD + col] = gu * h + (1.f - gu) * c;
                }
            }
            if (!last) {
                float c0v[4]; unpack4(aC0, c0v);
                reduceC<4>(c0v, sred, m, q);
                if (q == 0) {
                    float* s0n = g_s0buf[(t + 1) & 1];
#pragma unroll
                    for (int j = 0; j < 4; j++) {
                        int col = cc + j;
                        float c  = tanhf(c0v[j] +
                                   __ldg(X0n + (size_t)m * 3 * HIDD + 2 * HIDD + col));
                        float gu = __ldcg(g_gu0 + (size_t)m * HIDD + col);
                        float h  = __ldcg(s0c + (size_t)m * HIDD + col);
                        s0n[(size_t)m * HIDD + col] = gu * h + (1.f - gu) * c;
                    }
                }
            }
        }
        gridbar(tid, &s_sense);
    }
}

// ---------------- final state write ------------------------------------------
__global__ void write_state(float* __restrict__ out) {
    int idx = blockIdx.x * blockDim.x + threadIdx.x;
    if (idx < BB * HIDD) {
        size_t base = (size_t)BB * TT * VOCAB;
        out[base + idx] = g_s0buf[(TT - 1) & 1][idx];
        out[base + BB * HIDD + idx] = g_S1[(size_t)(TT - 1) * BB * HIDD + idx];
    }
}

// ---------------- host driver -------------------------------------------------
template <typename Sym>
static float* sym(Sym& s) {
    void* p = nullptr;
    cudaGetSymbolAddress(&p, s);
    return (float*)p;
}

extern "C" void kernel_launch(void* const* d_in, const int* in_sizes, int n_in,
                              void* d_out, int out_size) {
    const float* vgg     = (const float*)d_in[0];
    const int*   xTokens = (const int*)d_in[1];
    int i = 2;
    if (n_in >= 20 && in_sizes[2] == 1) i = 3;   // skip is_train scalar
    const float* emb   = (const float*)d_in[i++];
    const float* W_in  = (const float*)d_in[i++];
    const float* b_in  = (const float*)d_in[i++];
    const float* Wu0   = (const float*)d_in[i++];
    const float* bu0   = (const float*)d_in[i++];
    const float* Wr0   = (const float*)d_in[i++];
    const float* br0   = (const float*)d_in[i++];
    const float* Wc0   = (const float*)d_in[i++];
    const float* bc0   = (const float*)d_in[i++];
    const float* Wu1   = (const float*)d_in[i++];
    const float* bu1   = (const float*)d_in[i++];
    const float* Wr1   = (const float*)d_in[i++];
    const float* br1   = (const float*)d_in[i++];
    const float* Wc1   = (const float*)d_in[i++];
    const float* bc1   = (const float*)d_in[i++];
    const float* W_out = (const float*)d_in[i++];
    const float* b_out = (const float*)d_in[i++];
    float* out = (float*)d_out;

    float* pE     = sym(g_E);
    float* pX0    = sym(g_X0);
    float* pS1    = sym(g_S1);
    float* pW0top = sym(g_W0top);
    float* pB0top = sym(g_b0top);

    // 1) pack layer-0 top weights + biases
    pack_w0top<<<(HIDD * 3 * HIDD + 255) / 256, 256>>>(Wu0, Wr0, Wc0, bu0, br0, bc0);

    // 2) embedding gather
    embed_gather<<<TT * BB, 128>>>(emb, xTokens);

    // 3) X0 = E_all @ W0top + b0top   [3200,512]@[512,1536]
    sgemm_big<0><<<dim3(3 * HIDD / 128, TT * BB / 128), 256>>>(
        pE, pW0top, pB0top, pX0, TT * BB, 3 * HIDD, HIDD);

    // 4) persistent recurrence (h0 + 25 GRU steps, 2 barriers/step)
    {
        static int smem_set = 0;
        if (!smem_set) {
            cudaFuncSetAttribute(recur_kernel,
                                 cudaFuncAttributeMaxDynamicSharedMemorySize,
                                 SM_TOTALF * 4);
            smem_set = 1;
        }
        RP rp;
        rp.vgg = vgg; rp.W_in = W_in; rp.b_in = b_in;
        rp.Wu0 = Wu0; rp.Wr0 = Wr0; rp.Wc0 = Wc0;
        rp.Wu1 = Wu1; rp.Wr1 = Wr1; rp.Wc1 = Wc1;
        rp.bu1 = bu1; rp.br1 = br1; rp.bc1 = bc1;
        recur_kernel<<<GBLK, 512, SM_TOTALF * 4>>>(rp);
    }

    // 5) logits = S1 @ W_out + b_out, output rows in (b*T+t) order via A-remap
    sgemm_big<1><<<dim3((VOCAB + 127) / 128, TT * BB / 128), 256>>>(
        pS1, W_out, b_out, out, TT * BB, VOCAB, HIDD);

    // 6) final state [2, B, HID]
    write_state<<<(BB * HIDD + 255) / 256, 256>>>(out);
}

// round 13
// speedup vs baseline: 1.5792x; 1.0896x over previous
#include <cuda_runtime.h>
#include <math.h>

#define BB 128
#define TT 25
#define VOCAB 10000
#define EMBD 512
#define VGGD 4096
#define HIDD 512
#define GBLK 128

typedef unsigned long long u64;

// ---------------- packed f32x2 helpers (FFMA2: 2 MACs / instr) ---------------
__device__ __forceinline__ u64 pack2(float v) {
    u64 r; unsigned b = __float_as_uint(v);
    asm("mov.b64 %0, {%1, %1};" : "=l"(r) : "r"(b));
    return r;
}
__device__ __forceinline__ void fma2(u64& d, u64 a, u64 b) {
    asm("fma.rn.f32x2 %0, %1, %2, %0;" : "+l"(d) : "l"(a), "l"(b));
}
__device__ __forceinline__ float2 unpack2(u64 v) {
    unsigned lo, hi;
    asm("mov.b64 {%0, %1}, %2;" : "=r"(lo), "=r"(hi) : "l"(v));
    return make_float2(__uint_as_float(lo), __uint_as_float(hi));
}

__device__ __forceinline__ float fsel(const float4& a, int kk) {
    return kk == 0 ? a.x : kk == 1 ? a.y : kk == 2 ? a.z : a.w;
}

// ---------------- scratch (device globals; no allocation allowed) ------------
__device__ float g_h0[BB * HIDD];
__device__ float g_E[TT * BB * EMBD];
__device__ float g_X0[TT * BB * 3 * HIDD];     // [u|r|c] per row
__device__ float g_S1[TT * BB * HIDD];
__device__ float g_s0buf[2][BB * HIDD];
__device__ float g_gu0[BB * HIDD];
__device__ float g_gr0[BB * HIDD];
__device__ float g_gu1[BB * HIDD];
__device__ float g_gr1[BB * HIDD];
__device__ float g_W0top[HIDD * 3 * HIDD];
__device__ float g_b0top[3 * HIDD];
__device__ unsigned g_bar_count;
__device__ unsigned g_bar_sense;

// ---------------- pack layer-0 top weights -----------------------------------
__global__ void pack_w0top(const float* __restrict__ Wu0, const float* __restrict__ Wr0,
                           const float* __restrict__ Wc0, const float* __restrict__ bu0,
                           const float* __restrict__ br0, const float* __restrict__ bc0) {
    int idx = blockIdx.x * blockDim.x + threadIdx.x;
    const int total = HIDD * 3 * HIDD;
    if (idx < total) {
        int k = idx / (3 * HIDD);
        int j = idx - k * (3 * HIDD);
        float v;
        if (j < HIDD)           v = Wu0[k * HIDD + j];
        else if (j < 2 * HIDD)  v = Wr0[k * HIDD + (j - HIDD)];
        else                    v = Wc0[k * HIDD + (j - 2 * HIDD)];
        g_W0top[idx] = v;
    }
    if (idx < 3 * HIDD) {
        g_b0top[idx] = (idx < HIDD) ? bu0[idx]
                     : (idx < 2 * HIDD) ? br0[idx - HIDD]
                                        : bc0[idx - 2 * HIDD];
    }
}

// ---------------- embedding gather -------------------------------------------
__global__ void embed_gather(const float* __restrict__ emb, const int* __restrict__ tokens) {
    int r = blockIdx.x;
    int t = r / BB;
    int b = r - t * BB;
    int tok = tokens[b * TT + t];
    const float4* src = (const float4*)(emb + (size_t)tok * EMBD);
    float4* dst = (float4*)(g_E + (size_t)r * EMBD);
    dst[threadIdx.x] = src[threadIdx.x];
}

// ---------------- big tiled SGEMM: C = A@W + bias (FFMA2 core) ---------------
template <int AREMAP>
__global__ __launch_bounds__(256) void sgemm_big(
    const float* __restrict__ A, const float* __restrict__ W,
    const float* __restrict__ bias, float* __restrict__ C,
    int M, int N, int K)
{
    __shared__ float As[8][128];
    __shared__ float Ws[8][128];
    int tid = threadIdx.x;
    int m0 = blockIdx.y * 128;
    int n0 = blockIdx.x * 128;
    int tx = tid & 15;
    int ty = tid >> 4;

    u64 acc2[8][4];
#pragma unroll
    for (int i = 0; i < 8; i++)
#pragma unroll
        for (int j = 0; j < 4; j++) acc2[i][j] = 0ull;

    int lar = tid >> 1;
    int lak = (tid & 1) * 4;
    int arow = m0 + lar;
    if (AREMAP) arow = (arow % TT) * BB + (arow / TT);
    const float* Aptr = A + (size_t)arow * K;
    int lwk = tid >> 5;
    int lwc = (tid & 31) * 4;

    for (int k0 = 0; k0 < K; k0 += 8) {
        float4 av = *(const float4*)(Aptr + k0 + lak);
        As[lak + 0][lar] = av.x;
        As[lak + 1][lar] = av.y;
        As[lak + 2][lar] = av.z;
        As[lak + 3][lar] = av.w;

        int wn = n0 + lwc;
        const float* Wp = W + (size_t)(k0 + lwk) * N + wn;
        float4 wv;
        if (wn + 3 < N) {
            wv = *(const float4*)Wp;
        } else {
            wv.x = (wn + 0 < N) ? Wp[0] : 0.f;
            wv.y = (wn + 1 < N) ? Wp[1] : 0.f;
            wv.z = (wn + 2 < N) ? Wp[2] : 0.f;
            wv.w = (wn + 3 < N) ? Wp[3] : 0.f;
        }
        *(float4*)&Ws[lwk][lwc] = wv;
        __syncthreads();

#pragma unroll
        for (int kk = 0; kk < 8; kk++) {
            float4 a0 = *(const float4*)&As[kk][ty * 4];
            float4 a1 = *(const float4*)&As[kk][64 + ty * 4];
            float4 w0 = *(const float4*)&Ws[kk][tx * 4];
            float4 w1 = *(const float4*)&Ws[kk][64 + tx * 4];
            u64 wv2[4];
            wv2[0] = ((const u64*)&w0)[0]; wv2[1] = ((const u64*)&w0)[1];
            wv2[2] = ((const u64*)&w1)[0]; wv2[3] = ((const u64*)&w1)[1];
            float ar[8] = {a0.x, a0.y, a0.z, a0.w, a1.x, a1.y, a1.z, a1.w};
#pragma unroll
            for (int i = 0; i < 8; i++) {
                u64 pa = pack2(ar[i]);
                fma2(acc2[i][0], pa, wv2[0]);
                fma2(acc2[i][1], pa, wv2[1]);
                fma2(acc2[i][2], pa, wv2[2]);
                fma2(acc2[i][3], pa, wv2[3]);
            }
        }
        __syncthreads();
    }

#pragma unroll
    for (int i = 0; i < 8; i++) {
        int row = m0 + ((i < 4) ? (ty * 4 + i) : (64 + ty * 4 + i - 4));
        float* Crow = C + (size_t)row * N;
#pragma unroll
        for (int j = 0; j < 4; j++) {
            float2 v = unpack2(acc2[i][j]);
            int col = n0 + ((j < 2) ? (tx * 4 + j * 2) : (64 + tx * 4 + (j - 2) * 2));
            if (col < N)     Crow[col]     = v.x + bias[col];
            if (col + 1 < N) Crow[col + 1] = v.y + bias[col + 1];
        }
    }
}

// ================== persistent recurrence kernel =============================
struct RP {
    const float* vgg;
    const float* W_in; const float* b_in;
    const float* Wu0; const float* Wr0; const float* Wc0;
    const float* Wu1; const float* Wr1; const float* Wc1;
    const float* bu1; const float* br1; const float* bc1;
};

__device__ __forceinline__ void gridbar(int tid, unsigned* ps) {
    __threadfence();
    __syncthreads();
    if (tid == 0) {
        unsigned ns = *ps ^ 1u;
        *ps = ns;
        if (atomicAdd(&g_bar_count, 1u) == GBLK - 1) {
            *(volatile unsigned*)&g_bar_count = 0;
            __threadfence();
            *(volatile unsigned*)&g_bar_sense = ns;
        } else {
            while (*(volatile unsigned*)&g_bar_sense != ns) { }
        }
        __threadfence();
    }
    __syncthreads();
}

// ---- stage one 64-k A chunk [128 rows] into smem (coalesced, optional ⊙) ----
__device__ __forceinline__ void stageA64(float* dst, const float* __restrict__ s1,
                                         const float* __restrict__ s2,
                                         int kbase, int tid) {
#pragma unroll
    for (int i = 0; i < 4; i++) {
        int lin = tid + i * 512;
        int row = lin >> 4, f4 = (lin & 15) * 4;
        float4 v = __ldcg((const float4*)(s1 + (size_t)row * HIDD + kbase + f4));
        if (s2) {
            float4 b = __ldcg((const float4*)(s2 + (size_t)row * HIDD + kbase + f4));
            v.x *= b.x; v.y *= b.y; v.z *= b.z; v.w *= b.w;
        }
        *(float4*)(dst + row * 68 + f4) = v;
    }
}

// ---- gates accumulate: R=2 rows, C=8 cols, 8k slice of a 64-k chunk ---------
// warp wq (0..7) handles k-local wq*8..wq*8+7; rh selects row half.
__device__ __forceinline__ void gacc(u64 (&acc)[2][4], const float* sA,
                                     const float* sWk, int l, int wq, int rh) {
#pragma unroll
    for (int kb = 0; kb < 8; kb += 4) {
        int k0 = wq * 8 + kb;
        float4 a0 = *(const float4*)(sA + (l + 64 * rh) * 68 + k0);
        float4 a1 = *(const float4*)(sA + (l + 64 * rh + 32) * 68 + k0);
        const float* Wp = sWk + k0 * 8;
#pragma unroll
        for (int kk = 0; kk < 4; kk++) {
            float4 w01 = *(const float4*)(Wp + kk * 8);
            float4 w23 = *(const float4*)(Wp + kk * 8 + 4);
            u64 w[4] = {((const u64*)&w01)[0], ((const u64*)&w01)[1],
                        ((const u64*)&w23)[0], ((const u64*)&w23)[1]};
            u64 p0 = pack2(fsel(a0, kk));
            u64 p1 = pack2(fsel(a1, kk));
            fma2(acc[0][0], p0, w[0]); fma2(acc[0][1], p0, w[1]);
            fma2(acc[0][2], p0, w[2]); fma2(acc[0][3], p0, w[3]);
            fma2(acc[1][0], p1, w[0]); fma2(acc[1][1], p1, w[1]);
            fma2(acc[1][2], p1, w[2]); fma2(acc[1][3], p1, w[3]);
        }
    }
}

// ---- candidate accumulate: R=2 rows, C=4 cols -------------------------------
__device__ __forceinline__ void cacc(u64 (&acc)[2][2], const float* sA,
                                     const float* sWk, int l, int wq, int rh) {
#pragma unroll
    for (int kb = 0; kb < 8; kb += 4) {
        int k0 = wq * 8 + kb;
        float4 a0 = *(const float4*)(sA + (l + 64 * rh) * 68 + k0);
        float4 a1 = *(const float4*)(sA + (l + 64 * rh + 32) * 68 + k0);
        const float* Wp = sWk + k0 * 4;
#pragma unroll
        for (int kk = 0; kk < 4; kk++) {
            float4 wv = *(const float4*)(Wp + kk * 4);
            u64 w0 = ((const u64*)&wv)[0], w1 = ((const u64*)&wv)[1];
            u64 p0 = pack2(fsel(a0, kk));
            u64 p1 = pack2(fsel(a1, kk));
            fma2(acc[0][0], p0, w0); fma2(acc[0][1], p0, w1);
            fma2(acc[1][0], p1, w0); fma2(acc[1][1], p1, w1);
        }
    }
}

// ---- 8-way k-slice reduction (3 rounds), conflict-free padded strides -------
template <int NF, int STR>
__device__ __forceinline__ void redq(float* v, float* buf, int l, int wq, int rh) {
#pragma unroll 1
    for (int h = 4; h >= 1; h >>= 1) {
        __syncthreads();
        if (wq >= h && wq < 2 * h) {
            float* b = buf + (((wq - h) * 2 + rh) * 32 + l) * STR;
#pragma unroll
            for (int j = 0; j < NF; j += 4)
                *(float4*)(b + j) = make_float4(v[j], v[j + 1], v[j + 2], v[j + 3]);
        }
        __syncthreads();
        if (wq < h) {
            const float* b = buf + ((wq * 2 + rh) * 32 + l) * STR;
#pragma unroll
            for (int j = 0; j < NF; j++) v[j] += b[j];
        }
    }
}

__device__ __forceinline__ void unpG(const u64 (&a)[2][4], float (&v)[16]) {
#pragma unroll
    for (int r = 0; r < 2; r++)
#pragma unroll
        for (int c = 0; c < 4; c++) {
            float2 p = unpack2(a[r][c]);
            v[r * 8 + 2 * c] = p.x; v[r * 8 + 2 * c + 1] = p.y;
        }
}
__device__ __forceinline__ void unpC(const u64 (&a)[2][2], float (&v)[8]) {
#pragma unroll
    for (int r = 0; r < 2; r++)
#pragma unroll
        for (int c = 0; c < 2; c++) {
            float2 p = unpack2(a[r][c]);
            v[r * 4 + 2 * c] = p.x; v[r * 4 + 2 * c + 1] = p.y;
        }
}

// helpers for h0 (one-time, K=4096)
template <int KQ>
__device__ __forceinline__ void mm8t(u64 (&acc)[4], const float* pA,
                                     const float* __restrict__ gW) {
#pragma unroll 1
    for (int g = 0; g < KQ; g += 4) {
        float4 a = __ldcg((const float4*)(pA + g));
        const float* wp = gW + (size_t)g * HIDD;
#pragma unroll
        for (int j = 0; j < 4; j++) {
            float4 w01 = __ldg((const float4*)(wp + (size_t)j * HIDD));
            float4 w23 = __ldg((const float4*)(wp + (size_t)j * HIDD + 4));
            u64 pa = pack2(j == 0 ? a.x : j == 1 ? a.y : j == 2 ? a.z : a.w);
            fma2(acc[0], pa, ((const u64*)&w01)[0]);
            fma2(acc[1], pa, ((const u64*)&w01)[1]);
            fma2(acc[2], pa, ((const u64*)&w23)[0]);
            fma2(acc[3], pa, ((const u64*)&w23)[1]);
        }
    }
}
template <int MR, int Q>
__device__ __forceinline__ void reduceQ(float (&acc)[8], float* s, int m, int q) {
    __syncthreads();
    if (q > 0) {
        float* r = s + ((size_t)(q - 1) * MR + m) * 8;
        *(float4*)r       = make_float4(acc[0], acc[1], acc[2], acc[3]);
        *(float4*)(r + 4) = make_float4(acc[4], acc[5], acc[6], acc[7]);
    }
    __syncthreads();
    if (q == 0) {
#pragma unroll
        for (int qq = 1; qq < Q; qq++) {
            const float* r = s + ((size_t)(qq - 1) * MR + m) * 8;
#pragma unroll
            for (int j = 0; j < 8; j++) acc[j] += r[j];
        }
    }
}

__device__ __forceinline__ float sigm(float x) { return 1.f / (1.f + expf(-x)); }

// smem layout (floats)
#define SM_WG1   0
#define SM_WC1T  8192
#define SM_WC1B  10240
#define SM_WG0   12288
#define SM_WC0B  16384
#define SM_A0    18432
#define SM_A1    27136
#define SM_RED   35840
#define SM_TOTALF 40960

__global__ __launch_bounds__(512, 1) void recur_kernel(RP p) {
    extern __shared__ float sm[];
    float* sWg1  = sm + SM_WG1;
    float* sWc1t = sm + SM_WC1T;
    float* sWc1b = sm + SM_WC1B;
    float* sWg0  = sm + SM_WG0;
    float* sWc0b = sm + SM_WC0B;
    float* sA0   = sm + SM_A0;
    float* sA1   = sm + SM_A1;
    float* sred  = sm + SM_RED;
    __shared__ unsigned s_sense;

    int tid = threadIdx.x, bid = blockIdx.x;
    if (tid == 0) s_sense = *(volatile unsigned*)&g_bar_sense;

    const int l  = tid & 31;
    const int w  = tid >> 5;     // 0..15
    const int wq = w >> 1;       // k-slice 0..7
    const int rh = w & 1;        // row half
    const int c0g  = bid * 8;
    const int half = c0g >= HIDD;
    const int wcol = c0g & (HIDD - 1);
    const int cc   = bid * 4;

    // ---- stage all weight slices once (persist whole kernel) -------------
    {
        const float* Wg1 = half ? p.Wr1 : p.Wu1;
        for (int lin = tid; lin < 2048; lin += 512) {
            int k = lin >> 1, j4 = (lin & 1) * 4;
            *(float4*)(sWg1 + k * 8 + j4) =
                __ldg((const float4*)(Wg1 + (size_t)k * HIDD + wcol + j4));
        }
        const float* Wg0 = (half ? p.Wr0 : p.Wu0) + HIDD * HIDD;
        for (int lin = tid; lin < 1024; lin += 512) {
            int k = lin >> 1, j4 = (lin & 1) * 4;
            *(float4*)(sWg0 + k * 8 + j4) =
                __ldg((const float4*)(Wg0 + (size_t)k * HIDD + wcol + j4));
        }
        if (tid < 512) {
            int k = tid;
            *(float4*)(sWc1t + k * 4) =
                __ldg((const float4*)(p.Wc1 + (size_t)k * HIDD + cc));
            *(float4*)(sWc1b + k * 4) =
                __ldg((const float4*)(p.Wc1 + (size_t)(512 + k) * HIDD + cc));
            *(float4*)(sWc0b + k * 4) =
                __ldg((const float4*)(p.Wc0 + (size_t)(512 + k) * HIDD + cc));
        }
    }
    __syncthreads();

    // ---- h0 = tanh(vgg @ W_in + b_in)  MR=64, Q=8, K=4096 ----------------
    {
        int ct = bid >> 1, rg = bid & 1;
        int c0 = ct * 8;
        int hm = tid & 63, hq = tid >> 6;
        int row = rg * 64 + hm;
        const float* pA = p.vgg + (size_t)row * VGGD + hq * 512;
        const float* gW = p.W_in + (size_t)(hq * 512) * HIDD + c0;
        u64 a2[4] = {0, 0, 0, 0};
        mm8t<512>(a2, pA, gW);
        float acc[8];
#pragma unroll
        for (int j = 0; j < 4; j++) {
            float2 v = unpack2(a2[j]);
            acc[2 * j] = v.x; acc[2 * j + 1] = v.y;
        }
        reduceQ<64, 8>(acc, sred, hm, hq);
        if (hq == 0) {
#pragma unroll
            for (int j = 0; j < 8; j++)
                g_h0[row * HIDD + c0 + j] = tanhf(acc[j] + __ldg(p.b_in + c0 + j));
        }
    }
    gridbar(tid, &s_sense);

    // ---- prologue 1: gates0(0) from h0 -----------------------------------
    {
        u64 aG0[2][4] = {};
        for (int ch = 0; ch < 8; ch++) {
            stageA64(sA0, g_h0, nullptr, ch * 64, tid);
            __syncthreads();
            gacc(aG0, sA0, sWg0 + ch * 64 * 8, l, wq, rh);
            __syncthreads();
        }
        float v[16]; unpG(aG0, v);
        redq<16, 20>(v, sred, l, wq, rh);
        if (wq == 0) {
            float* out = half ? g_gr0 : g_gu0;
#pragma unroll
            for (int r = 0; r < 2; r++) {
                int row = l + 64 * rh + 32 * r;
#pragma unroll
                for (int j = 0; j < 8; j++)
                    out[row * HIDD + wcol + j] =
                        sigm(v[r * 8 + j] + __ldcg(g_X0 + (size_t)row * 3 * HIDD + c0g + j));
            }
        }
    }
    gridbar(tid, &s_sense);

    // ---- prologue 2: s0cur(0) --------------------------------------------
    {
        u64 aC0[2][2] = {};
        for (int ch = 0; ch < 8; ch++) {
            stageA64(sA0, g_gr0, g_h0, ch * 64, tid);
            __syncthreads();
            cacc(aC0, sA0, sWc0b + ch * 64 * 4, l, wq, rh);
            __syncthreads();
        }
        float v[8]; unpC(aC0, v);
        redq<8, 12>(v, sred, l, wq, rh);
        if (wq == 0) {
#pragma unroll
            for (int r = 0; r < 2; r++) {
                int row = l + 64 * rh + 32 * r;
#pragma unroll
                for (int j = 0; j < 4; j++) {
                    int col = cc + j;
                    float c  = tanhf(v[r * 4 + j] +
                               __ldcg(g_X0 + (size_t)row * 3 * HIDD + 2 * HIDD + col));
                    float gu = __ldcg(g_gu0 + (size_t)row * HIDD + col);
                    float h  = __ldcg(g_h0 + (size_t)row * HIDD + col);
                    g_s0buf[0][(size_t)row * HIDD + col] = gu * h + (1.f - gu) * c;
                }
            }
        }
    }
    gridbar(tid, &s_sense);

    // ---- main loop: 2 barriers / step ------------------------------------
#pragma unroll 1
    for (int t = 0; t < TT; t++) {
        const float* s0c = g_s0buf[t & 1];
        const float* s1p = t ? (g_S1 + (size_t)(t - 1) * BB * HIDD) : g_h0;
        const float* X0n = g_X0 + (size_t)(t + 1) * BB * 3 * HIDD;
        const bool last = (t == TT - 1);

        u64 aC1[2][2] = {};

        // ===== PhA: gates1(t) + c1-top(t) + gates0(t+1) =====
        {
            u64 aG1[2][4] = {};
            u64 aG0[2][4] = {};
            for (int ch = 0; ch < 8; ch++) {
                stageA64(sA0, s0c, nullptr, ch * 64, tid);
                stageA64(sA1, s1p, nullptr, ch * 64, tid);
                __syncthreads();
                gacc(aG1, sA0, sWg1 + ch * 64 * 8, l, wq, rh);
                gacc(aG1, sA1, sWg1 + (512 + ch * 64) * 8, l, wq, rh);
                cacc(aC1, sA0, sWc1t + ch * 64 * 4, l, wq, rh);
                if (!last)
                    gacc(aG0, sA0, sWg0 + ch * 64 * 8, l, wq, rh);
                __syncthreads();
            }
            float v1[16]; unpG(aG1, v1);
            redq<16, 20>(v1, sred, l, wq, rh);
            if (wq == 0) {
                const float* b = half ? p.br1 : p.bu1;
                float* out = half ? g_gr1 : g_gu1;
#pragma unroll
                for (int r = 0; r < 2; r++) {
                    int row = l + 64 * rh + 32 * r;
#pragma unroll
                    for (int j = 0; j < 8; j++)
                        out[row * HIDD + wcol + j] =
                            sigm(v1[r * 8 + j] + __ldg(b + wcol + j));
                }
            }
            if (!last) {
                float v0[16]; unpG(aG0, v0);
                redq<16, 20>(v0, sred, l, wq, rh);
                if (wq == 0) {
                    float* out = half ? g_gr0 : g_gu0;
#pragma unroll
                    for (int r = 0; r < 2; r++) {
                        int row = l + 64 * rh + 32 * r;
#pragma unroll
                        for (int j = 0; j < 8; j++)
                            out[row * HIDD + wcol + j] =
                                sigm(v0[r * 8 + j] +
                                     __ldcg(X0n + (size_t)row * 3 * HIDD + c0g + j));
                    }
                }
            }
        }
        gridbar(tid, &s_sense);

        // ===== PhB: s1cur(t) + s0cur(t+1) =====
        {
            u64 aC0[2][2] = {};
            for (int ch = 0; ch < 8; ch++) {
                stageA64(sA0, g_gr1, s1p, ch * 64, tid);
                if (!last) stageA64(sA1, g_gr0, s0c, ch * 64, tid);
                __syncthreads();
                cacc(aC1, sA0, sWc1b + ch * 64 * 4, l, wq, rh);
                if (!last)
                    cacc(aC0, sA1, sWc0b + ch * 64 * 4, l, wq, rh);
                __syncthreads();
            }
            float v[8]; unpC(aC1, v);
            redq<8, 12>(v, sred, l, wq, rh);
            if (wq == 0) {
                float* s1cur = g_S1 + (size_t)t * BB * HIDD;
#pragma unroll
                for (int r = 0; r < 2; r++) {
                    int row = l + 64 * rh + 32 * r;
#pragma unroll
                    for (int j = 0; j < 4; j++) {
                        int col = cc + j;
                        float c  = tanhf(v[r * 4 + j] + __ldg(p.bc1 + col));
                        float gu = __ldcg(g_gu1 + (size_t)row * HIDD + col);
                        float h  = __ldcg(s1p + (size_t)row * HIDD + col);
                        s1cur[(size_t)row * HIDD + col] = gu * h + (1.f - gu) * c;
                    }
                }
            }
            if (!last) {
                float v0[8]; unpC(aC0, v0);
                redq<8, 12>(v0, sred, l, wq, rh);
                if (wq == 0) {
                    float* s0n = g_s0buf[(t + 1) & 1];
#pragma unroll
                    for (int r = 0; r < 2; r++) {
                        int row = l + 64 * rh + 32 * r;
#pragma unroll
                        for (int j = 0; j < 4; j++) {
                            int col = cc + j;
                            float c  = tanhf(v0[r * 4 + j] +
                                       __ldcg(X0n + (size_t)row * 3 * HIDD + 2 * HIDD + col));
                            float gu = __ldcg(g_gu0 + (size_t)row * HIDD + col);
                            float h  = __ldcg(s0c + (size_t)row * HIDD + col);
                            s0n[(size_t)row * HIDD + col] = gu * h + (1.f - gu) * c;
                        }
                    }
                }
            }
        }
        gridbar(tid, &s_sense);
    }
}

// ---------------- final state write ------------------------------------------
__global__ void write_state(float* __restrict__ out) {
    int idx = blockIdx.x * blockDim.x + threadIdx.x;
    if (idx < BB * HIDD) {
        size_t base = (size_t)BB * TT * VOCAB;
        out[base + idx] = g_s0buf[(TT - 1) & 1][idx];
        out[base + BB * HIDD + idx] = g_S1[(size_t)(TT - 1) * BB * HIDD + idx];
    }
}

// ---------------- host driver -------------------------------------------------
template <typename Sym>
static float* sym(Sym& s) {
    void* p = nullptr;
    cudaGetSymbolAddress(&p, s);
    return (float*)p;
}

extern "C" void kernel_launch(void* const* d_in, const int* in_sizes, int n_in,
                              void* d_out, int out_size) {
    const float* vgg     = (const float*)d_in[0];
    const int*   xTokens = (const int*)d_in[1];
    int i = 2;
    if (n_in >= 20 && in_sizes[2] == 1) i = 3;   // skip is_train scalar
    const float* emb   = (const float*)d_in[i++];
    const float* W_in  = (const float*)d_in[i++];
    const float* b_in  = (const float*)d_in[i++];
    const float* Wu0   = (const float*)d_in[i++];
    const float* bu0   = (const float*)d_in[i++];
    const float* Wr0   = (const float*)d_in[i++];
    const float* br0   = (const float*)d_in[i++];
    const float* Wc0   = (const float*)d_in[i++];
    const float* bc0   = (const float*)d_in[i++];
    const float* Wu1   = (const float*)d_in[i++];
    const float* bu1   = (const float*)d_in[i++];
    const float* Wr1   = (const float*)d_in[i++];
    const float* br1   = (const float*)d_in[i++];
    const float* Wc1   = (const float*)d_in[i++];
    const float* bc1   = (const float*)d_in[i++];
    const float* W_out = (const float*)d_in[i++];
    const float* b_out = (const float*)d_in[i++];
    float* out = (float*)d_out;

    float* pE     = sym(g_E);
    float* pX0    = sym(g_X0);
    float* pS1    = sym(g_S1);
    float* pW0top = sym(g_W0top);
    float* pB0top = sym(g_b0top);

    // 1) pack layer-0 top weights + biases
    pack_w0top<<<(HIDD * 3 * HIDD + 255) / 256, 256>>>(Wu0, Wr0, Wc0, bu0, br0, bc0);

    // 2) embedding gather
    embed_gather<<<TT * BB, 128>>>(emb, xTokens);

    // 3) X0 = E_all @ W0top + b0top   [3200,512]@[512,1536]
    sgemm_big<0><<<dim3(3 * HIDD / 128, TT * BB / 128), 256>>>(
        pE, pW0top, pB0top, pX0, TT * BB, 3 * HIDD, HIDD);

    // 4) persistent recurrence (h0 + 25 GRU steps, 2 barriers/step)
    {
        static int smem_set = 0;
        if (!smem_set) {
            cudaFuncSetAttribute(recur_kernel,
                                 cudaFuncAttributeMaxDynamicSharedMemorySize,
                                 SM_TOTALF * 4);
            smem_set = 1;
        }
        RP rp;
        rp.vgg = vgg; rp.W_in = W_in; rp.b_in = b_in;
        rp.Wu0 = Wu0; rp.Wr0 = Wr0; rp.Wc0 = Wc0;
        rp.Wu1 = Wu1; rp.Wr1 = Wr1; rp.Wc1 = Wc1;
        rp.bu1 = bu1; rp.br1 = br1; rp.bc1 = bc1;
        recur_kernel<<<GBLK, 512, SM_TOTALF * 4>>>(rp);
    }

    // 5) logits = S1 @ W_out + b_out, output rows in (b*T+t) order via A-remap
    sgemm_big<1><<<dim3((VOCAB + 127) / 128, TT * BB / 128), 256>>>(
        pS1, W_out, b_out, out, TT * BB, VOCAB, HIDD);

    // 6) final state [2, B, HID]
    write_state<<<(BB * HIDD + 255) / 256, 256>>>(out);
}